// round 12
// baseline (speedup 1.0000x reference)
#include <cuda_runtime.h>
#include <cuda_bf16.h>

// Problem shape (fixed by reference setup_inputs)
#define B 64
#define T 4096
#define H 512

#define OCHUNKS 4            // o-split across blocks in proj
#define NTILE   64           // t-values per scores block
#define NTILES  (T / NTILE)  // 64 tiles per b

// Scratch (no allocation allowed in kernel_launch)
__device__ float  g_vpart[OCHUNKS][B][H];   // partial v per o-chunk
__device__ float  g_scores[B * T];          // raw scores [B, T]
__device__ float2 g_bpart[B][NTILES];       // per-(b,tile) (max, sumexp)

// online-softmax combine
__device__ __forceinline__ float2 sm_combine(float2 a, float2 c) {
    const float m = fmaxf(a.x, c.x);
    float2 r;
    r.x = m;
    r.y = a.y * __expf(a.x - m) + c.y * __expf(c.x - m);
    return r;
}

// ---------------------------------------------------------------------------
// Kernel 1: partial v: g_vpart[z][b,h] = sum_{o in chunk z} hidden[b,o]*W[o,h]
// Grid: (H/32, B/4, 4) = 1024 blocks x 256 threads. BTILE=4, hidden staged
// transposed as float4 (1 broadcast LDS.128 per o-step). W L2 traffic = 16MB.
// ---------------------------------------------------------------------------
__global__ void __launch_bounds__(256, 8)
proj_hidden_kernel(const float* __restrict__ hidden,
                   const float* __restrict__ W) {
    const int b0 = blockIdx.y * 4;
    const int h0 = blockIdx.x * 32;
    const int oc = blockIdx.z;            // o-chunk, 128 o's
    const int hl = threadIdx.x & 31;      // h lane
    const int og = threadIdx.x >> 5;      // o-group 0..7 (warp-uniform)

    __shared__ float4 shv[128];           // shv[o] = {h[b0..b0+3] at o}
    {
        const int r = threadIdx.x >> 6;           // 0..3 (b row)
        const int c = threadIdx.x & 63;           // float2 slot
        const float2 hv = reinterpret_cast<const float2*>(
            hidden + (size_t)(b0 + r) * H + oc * 128)[c];
        reinterpret_cast<float*>(&shv[2 * c])[r]     = hv.x;
        reinterpret_cast<float*>(&shv[2 * c + 1])[r] = hv.y;
    }
    __syncthreads();

    const int obase = oc * 128 + og * 16;
    const float* __restrict__ wp = W + (size_t)obase * H + h0 + hl;
    const int ol = og * 16;
    float acc0 = 0.0f, acc1 = 0.0f, acc2 = 0.0f, acc3 = 0.0f;
#pragma unroll
    for (int o = 0; o < 16; ++o) {
        const float  w = wp[(size_t)o * H];
        const float4 h4 = shv[ol + o];    // broadcast, conflict-free
        acc0 += h4.x * w;
        acc1 += h4.y * w;
        acc2 += h4.z * w;
        acc3 += h4.w * w;
    }

    __shared__ float part[8][4][32];
    part[og][0][hl] = acc0;
    part[og][1][hl] = acc1;
    part[og][2][hl] = acc2;
    part[og][3][hl] = acc3;
    __syncthreads();
    if (threadIdx.x < 128) {
        const int bb = threadIdx.x >> 5;   // 0..3
        const int hh = threadIdx.x & 31;
        float r = 0.0f;
#pragma unroll
        for (int g = 0; g < 8; ++g) r += part[g][bb][hh];
        g_vpart[oc][b0 + bb][h0 + hh] = r;
    }
}

// ---------------------------------------------------------------------------
// Kernel 2: scores[b,t] = enc[b,t,:] . v[b,:]. The per-t shuffle reduce is
// REMOVED from the load path: each lane stores its 16-element partial to
// padded smem (conflict-free STS), so the inner loop is pure LDG+FFMA+STS and
// ptxas pipelines t+1 loads under t FMAs. One block tail reduces all 64 t's
// (4 threads/t), then the (m,sumexp) tile partial. __ldcs enc stream.
// ---------------------------------------------------------------------------
__global__ void __launch_bounds__(256)
scores_kernel(const float* __restrict__ enc) {
    const int b    = blockIdx.y;
    const int tile = blockIdx.x;          // 64 t-values per block
    const int tid  = threadIdx.x;         // 256
    const int warp = tid >> 5;
    const int lane = tid & 31;

    __shared__ float sv[H];
    {
        const float2 p0 = reinterpret_cast<const float2*>(g_vpart[0][b])[tid];
        const float2 p1 = reinterpret_cast<const float2*>(g_vpart[1][b])[tid];
        const float2 p2 = reinterpret_cast<const float2*>(g_vpart[2][b])[tid];
        const float2 p3 = reinterpret_cast<const float2*>(g_vpart[3][b])[tid];
        float2 s;
        s.x = (p0.x + p1.x) + (p2.x + p3.x);
        s.y = (p0.y + p1.y) + (p2.y + p3.y);
        reinterpret_cast<float2*>(sv)[tid] = s;
    }
    __syncthreads();

    const float4* __restrict__ vb = reinterpret_cast<const float4*>(sv);
    const float4* __restrict__ base =
        reinterpret_cast<const float4*>(enc + (size_t)b * T * H);

    __shared__ float s_part[64][33];      // [t_local][lane], padded
    __shared__ float s_acc[64];           // reduced raw scores

#pragma unroll
    for (int i = 0; i < 8; ++i) {
        const int tl = warp * 8 + i;
        const float4* __restrict__ row =
            base + (size_t)(tile * 64 + tl) * (H / 4);

        float acc = 0.0f;
#pragma unroll
        for (int k = 0; k < 4; ++k) {
            const float4 x = __ldcs(row + lane + k * 32);
            const float4 w = vb[lane + k * 32];
            acc += x.x * w.x + x.y * w.y + x.z * w.z + x.w * w.w;
        }
        s_part[tl][lane] = acc;           // no reduce on the load path
    }

    // block tail 1: reduce 32 lane-partials per t (4 threads per t)
    __syncthreads();
    {
        const int tl = tid >> 2;          // 0..63
        const int q  = tid & 3;
        float p = 0.0f;
#pragma unroll
        for (int j = 0; j < 8; ++j) p += s_part[tl][q * 8 + j];
        p += __shfl_xor_sync(0xffffffffu, p, 1);
        p += __shfl_xor_sync(0xffffffffu, p, 2);
        if (q == 0) {
            g_scores[b * T + tile * 64 + tl] = p;
            s_acc[tl] = p;
        }
    }

    // block tail 2: (m, sumexp) over the 64 scores
    __syncthreads();
    if (tid < 32) {
        const float v0 = s_acc[tid];
        const float v1 = s_acc[tid + 32];
        float m = fmaxf(v0, v1);
#pragma unroll
        for (int off = 16; off; off >>= 1)
            m = fmaxf(m, __shfl_xor_sync(0xffffffffu, m, off));
        float e = __expf(v0 - m) + __expf(v1 - m);
#pragma unroll
        for (int off = 16; off; off >>= 1)
            e += __shfl_xor_sync(0xffffffffu, e, off);
        if (tid == 0) {
            float2 r; r.x = m; r.y = e;
            g_bpart[b][tile] = r;
        }
    }
}

// ---------------------------------------------------------------------------
// Kernel 3: scale pass. Grid (T/1024, B) = 256 blocks x 256 threads.
// Combine the 64 tile partials (L2 hits), then exp(x-m)/S, float4/thread.
// ---------------------------------------------------------------------------
__global__ void scale_kernel(float* __restrict__ out) {
    const int b   = blockIdx.y;
    const int seg = blockIdx.x;           // 1024 t-values per block
    const int tid = threadIdx.x;          // 256

    __shared__ float2 ms;
    if (tid < 32) {
        float2 v = sm_combine(g_bpart[b][tid], g_bpart[b][tid + 32]);
#pragma unroll
        for (int off = 16; off; off >>= 1) {
            float2 o;
            o.x = __shfl_xor_sync(0xffffffffu, v.x, off);
            o.y = __shfl_xor_sync(0xffffffffu, v.y, off);
            v = sm_combine(v, o);
        }
        if (tid == 0) ms = v;
    }
    __syncthreads();

    const float m   = ms.x;
    const float inv = 1.0f / ms.y;

    const int idx = b * T + seg * 1024 + tid * 4;
    const float4 x = *reinterpret_cast<const float4*>(g_scores + idx);
    float4 y;
    y.x = __expf(x.x - m) * inv;
    y.y = __expf(x.y - m) * inv;
    y.z = __expf(x.z - m) * inv;
    y.w = __expf(x.w - m) * inv;
    *reinterpret_cast<float4*>(out + idx) = y;
}

// ---------------------------------------------------------------------------
extern "C" void kernel_launch(void* const* d_in, const int* in_sizes, int n_in,
                              void* d_out, int out_size) {
    const float* hidden = (const float*)d_in[0];   // [B, H]
    const float* enc    = (const float*)d_in[1];   // [B, T, H]
    const float* W      = (const float*)d_in[2];   // [H, H]
    // d_in[3] = bias: cancels under softmax, unused.
    float* out = (float*)d_out;                    // [B, 1, T]

    {
        dim3 grid(H / 32, B / 4, OCHUNKS);
        proj_hidden_kernel<<<grid, 256>>>(hidden, W);
    }
    {
        dim3 grid(T / NTILE, B);
        scores_kernel<<<grid, 256>>>(enc);
    }
    {
        dim3 grid(T / 1024, B);
        scale_kernel<<<grid, 256>>>(out);
    }
}

// round 13
// speedup vs baseline: 1.0233x; 1.0233x over previous
#include <cuda_runtime.h>
#include <cuda_bf16.h>

// Problem shape (fixed by reference setup_inputs)
#define B 64
#define T 4096
#define H 512

#define OCHUNKS 4            // o-split across blocks in proj
#define NTILE   128          // t-values per scores block (512 threads)
#define NTILES  (T / NTILE)  // 32 tiles per b

// Scratch (no allocation allowed in kernel_launch)
__device__ float  g_vpart[OCHUNKS][B][H];   // partial v per o-chunk
__device__ float  g_scores[B * T];          // raw scores [B, T]
__device__ float2 g_bpart[B][NTILES];       // per-(b,tile) (max, sumexp)

// online-softmax combine
__device__ __forceinline__ float2 sm_combine(float2 a, float2 c) {
    const float m = fmaxf(a.x, c.x);
    float2 r;
    r.x = m;
    r.y = a.y * __expf(a.x - m) + c.y * __expf(c.x - m);
    return r;
}

// ---------------------------------------------------------------------------
// Kernel 1: partial v: g_vpart[z][b,h] = sum_{o in chunk z} hidden[b,o]*W[o,h]
// Grid: (H/32, B/4, 4) = 1024 blocks x 256 threads. BTILE=4, hidden staged
// transposed as float4 (1 broadcast LDS.128 per o-step). W L2 traffic = 16MB.
// (Proven config, ~6.3-6.5us.)
// ---------------------------------------------------------------------------
__global__ void __launch_bounds__(256, 8)
proj_hidden_kernel(const float* __restrict__ hidden,
                   const float* __restrict__ W) {
    const int b0 = blockIdx.y * 4;
    const int h0 = blockIdx.x * 32;
    const int oc = blockIdx.z;            // o-chunk, 128 o's
    const int hl = threadIdx.x & 31;      // h lane
    const int og = threadIdx.x >> 5;      // o-group 0..7 (warp-uniform)

    __shared__ float4 shv[128];           // shv[o] = {h[b0..b0+3] at o}
    {
        const int r = threadIdx.x >> 6;           // 0..3 (b row)
        const int c = threadIdx.x & 63;           // float2 slot
        const float2 hv = reinterpret_cast<const float2*>(
            hidden + (size_t)(b0 + r) * H + oc * 128)[c];
        reinterpret_cast<float*>(&shv[2 * c])[r]     = hv.x;
        reinterpret_cast<float*>(&shv[2 * c + 1])[r] = hv.y;
    }
    __syncthreads();

    const int obase = oc * 128 + og * 16;
    const float* __restrict__ wp = W + (size_t)obase * H + h0 + hl;
    const int ol = og * 16;
    float acc0 = 0.0f, acc1 = 0.0f, acc2 = 0.0f, acc3 = 0.0f;
#pragma unroll
    for (int o = 0; o < 16; ++o) {
        const float  w = wp[(size_t)o * H];
        const float4 h4 = shv[ol + o];    // broadcast, conflict-free
        acc0 += h4.x * w;
        acc1 += h4.y * w;
        acc2 += h4.z * w;
        acc3 += h4.w * w;
    }

    __shared__ float part[8][4][32];
    part[og][0][hl] = acc0;
    part[og][1][hl] = acc1;
    part[og][2][hl] = acc2;
    part[og][3][hl] = acc3;
    __syncthreads();
    if (threadIdx.x < 128) {
        const int bb = threadIdx.x >> 5;   // 0..3
        const int hh = threadIdx.x & 31;
        float r = 0.0f;
#pragma unroll
        for (int g = 0; g < 8; ++g) r += part[g][bb][hh];
        g_vpart[oc][b0 + bb][h0 + hh] = r;
    }
}

// ---------------------------------------------------------------------------
// Kernel 2: scores[b,t] = enc[b,t,:] . v[b,:].
// Grid: (T/128, B) = 2048 blocks x 512 threads = 16 warps; each warp owns 8
// consecutive t, ONE at a time with the shfl reduce IN the loop (MLP_p1=4 —
// both higher-MLP variants regressed via cross-CTA L1tex spread). Warp-level
// structure identical to the proven 86.1us version; only the block is 2x,
// halving per-block staging traffic and prologue count.
// ---------------------------------------------------------------------------
__global__ void __launch_bounds__(512)
scores_kernel(const float* __restrict__ enc) {
    const int b    = blockIdx.y;
    const int tile = blockIdx.x;          // 128 t-values per block
    const int tid  = threadIdx.x;         // 512
    const int warp = tid >> 5;
    const int lane = tid & 31;

    __shared__ float sv[H];
    if (tid < 256) {
        const float2 p0 = reinterpret_cast<const float2*>(g_vpart[0][b])[tid];
        const float2 p1 = reinterpret_cast<const float2*>(g_vpart[1][b])[tid];
        const float2 p2 = reinterpret_cast<const float2*>(g_vpart[2][b])[tid];
        const float2 p3 = reinterpret_cast<const float2*>(g_vpart[3][b])[tid];
        float2 s;
        s.x = (p0.x + p1.x) + (p2.x + p3.x);
        s.y = (p0.y + p1.y) + (p2.y + p3.y);
        reinterpret_cast<float2*>(sv)[tid] = s;
    }
    __syncthreads();

    const float4* __restrict__ vb = reinterpret_cast<const float4*>(sv);
    const float4* __restrict__ base =
        reinterpret_cast<const float4*>(enc + (size_t)b * T * H);

    __shared__ float s_acc[NTILE];        // this block's raw scores

#pragma unroll
    for (int i = 0; i < 8; ++i) {
        const int tl = warp * 8 + i;      // 0..127
        const float4* __restrict__ row =
            base + (size_t)(tile * NTILE + tl) * (H / 4);

        float acc = 0.0f;
#pragma unroll
        for (int k = 0; k < 4; ++k) {
            const float4 x = __ldcs(row + lane + k * 32);
            const float4 w = vb[lane + k * 32];
            acc += x.x * w.x + x.y * w.y + x.z * w.z + x.w * w.w;
        }
#pragma unroll
        for (int off = 16; off; off >>= 1)
            acc += __shfl_xor_sync(0xffffffffu, acc, off);
        if (lane == 0) {
            g_scores[b * T + tile * NTILE + tl] = acc;
            s_acc[tl] = acc;
        }
    }

    // block tail: (m, sumexp) over the 128 scores (off the load path)
    __syncthreads();
    if (tid < 32) {
        const float v0 = s_acc[tid];
        const float v1 = s_acc[tid + 32];
        const float v2 = s_acc[tid + 64];
        const float v3 = s_acc[tid + 96];
        float m = fmaxf(fmaxf(v0, v1), fmaxf(v2, v3));
#pragma unroll
        for (int off = 16; off; off >>= 1)
            m = fmaxf(m, __shfl_xor_sync(0xffffffffu, m, off));
        float e = (__expf(v0 - m) + __expf(v1 - m))
                + (__expf(v2 - m) + __expf(v3 - m));
#pragma unroll
        for (int off = 16; off; off >>= 1)
            e += __shfl_xor_sync(0xffffffffu, e, off);
        if (tid == 0) {
            float2 r; r.x = m; r.y = e;
            g_bpart[b][tile] = r;
        }
    }
}

// ---------------------------------------------------------------------------
// Kernel 3: scale pass. Grid (T/1024, B) = 256 blocks x 256 threads.
// Combine the 32 tile partials (L2 hits), then exp(x-m)/S, float4/thread.
// ---------------------------------------------------------------------------
__global__ void scale_kernel(float* __restrict__ out) {
    const int b   = blockIdx.y;
    const int seg = blockIdx.x;           // 1024 t-values per block
    const int tid = threadIdx.x;          // 256

    __shared__ float2 ms;
    if (tid < 32) {
        float2 v = g_bpart[b][tid];
#pragma unroll
        for (int off = 16; off; off >>= 1) {
            float2 o;
            o.x = __shfl_xor_sync(0xffffffffu, v.x, off);
            o.y = __shfl_xor_sync(0xffffffffu, v.y, off);
            v = sm_combine(v, o);
        }
        if (tid == 0) ms = v;
    }
    __syncthreads();

    const float m   = ms.x;
    const float inv = 1.0f / ms.y;

    const int idx = b * T + seg * 1024 + tid * 4;
    const float4 x = *reinterpret_cast<const float4*>(g_scores + idx);
    float4 y;
    y.x = __expf(x.x - m) * inv;
    y.y = __expf(x.y - m) * inv;
    y.z = __expf(x.z - m) * inv;
    y.w = __expf(x.w - m) * inv;
    *reinterpret_cast<float4*>(out + idx) = y;
}

// ---------------------------------------------------------------------------
extern "C" void kernel_launch(void* const* d_in, const int* in_sizes, int n_in,
                              void* d_out, int out_size) {
    const float* hidden = (const float*)d_in[0];   // [B, H]
    const float* enc    = (const float*)d_in[1];   // [B, T, H]
    const float* W      = (const float*)d_in[2];   // [H, H]
    // d_in[3] = bias: cancels under softmax, unused.
    float* out = (float*)d_out;                    // [B, 1, T]

    {
        dim3 grid(H / 32, B / 4, OCHUNKS);
        proj_hidden_kernel<<<grid, 256>>>(hidden, W);
    }
    {
        dim3 grid(T / NTILE, B);
        scores_kernel<<<grid, 512>>>(enc);
    }
    {
        dim3 grid(T / 1024, B);
        scale_kernel<<<grid, 256>>>(out);
    }
}

// round 14
// speedup vs baseline: 1.0290x; 1.0056x over previous
#include <cuda_runtime.h>
#include <cuda_bf16.h>

// Problem shape (fixed by reference setup_inputs)
#define B 64
#define T 4096
#define H 512

#define OCHUNKS 4            // o-split across blocks in proj
#define NTILE   64           // t-values per scores block
#define NTILES  (T / NTILE)  // 64 tiles per b

// Scratch (no allocation allowed in kernel_launch)
__device__ float  g_vpart[OCHUNKS][B][H];   // partial v per o-chunk
__device__ float  g_scores[B * T];          // raw scores [B, T]
__device__ float2 g_bpart[B][NTILES];       // per-(b,tile) (max, sumexp)

// PDL: wait for the upstream grid's completion trigger (sm_90+)
__device__ __forceinline__ void griddep_wait() {
    asm volatile("griddepcontrol.wait;" ::: "memory");
}

// online-softmax combine
__device__ __forceinline__ float2 sm_combine(float2 a, float2 c) {
    const float m = fmaxf(a.x, c.x);
    float2 r;
    r.x = m;
    r.y = a.y * __expf(a.x - m) + c.y * __expf(c.x - m);
    return r;
}

// ---------------------------------------------------------------------------
// Kernel 1: partial v: g_vpart[z][b,h] = sum_{o in chunk z} hidden[b,o]*W[o,h]
// Grid: (H/32, B/4, 4) = 1024 blocks x 256 threads. BTILE=4, hidden staged
// transposed as float4 (1 broadcast LDS.128 per o-step). W L2 traffic = 16MB.
// ---------------------------------------------------------------------------
__global__ void __launch_bounds__(256, 8)
proj_hidden_kernel(const float* __restrict__ hidden,
                   const float* __restrict__ W) {
    const int b0 = blockIdx.y * 4;
    const int h0 = blockIdx.x * 32;
    const int oc = blockIdx.z;            // o-chunk, 128 o's
    const int hl = threadIdx.x & 31;      // h lane
    const int og = threadIdx.x >> 5;      // o-group 0..7 (warp-uniform)

    __shared__ float4 shv[128];           // shv[o] = {h[b0..b0+3] at o}
    {
        const int r = threadIdx.x >> 6;           // 0..3 (b row)
        const int c = threadIdx.x & 63;           // float2 slot
        const float2 hv = reinterpret_cast<const float2*>(
            hidden + (size_t)(b0 + r) * H + oc * 128)[c];
        reinterpret_cast<float*>(&shv[2 * c])[r]     = hv.x;
        reinterpret_cast<float*>(&shv[2 * c + 1])[r] = hv.y;
    }
    __syncthreads();

    const int obase = oc * 128 + og * 16;
    const float* __restrict__ wp = W + (size_t)obase * H + h0 + hl;
    const int ol = og * 16;
    float acc0 = 0.0f, acc1 = 0.0f, acc2 = 0.0f, acc3 = 0.0f;
#pragma unroll
    for (int o = 0; o < 16; ++o) {
        const float  w = wp[(size_t)o * H];
        const float4 h4 = shv[ol + o];    // broadcast, conflict-free
        acc0 += h4.x * w;
        acc1 += h4.y * w;
        acc2 += h4.z * w;
        acc3 += h4.w * w;
    }

    __shared__ float part[8][4][32];
    part[og][0][hl] = acc0;
    part[og][1][hl] = acc1;
    part[og][2][hl] = acc2;
    part[og][3][hl] = acc3;
    __syncthreads();
    if (threadIdx.x < 128) {
        const int bb = threadIdx.x >> 5;   // 0..3
        const int hh = threadIdx.x & 31;
        float r = 0.0f;
#pragma unroll
        for (int g = 0; g < 8; ++g) r += part[g][bb][hh];
        g_vpart[oc][b0 + bb][h0 + hh] = r;
    }
}

// ---------------------------------------------------------------------------
// Kernel 2: scores[b,t] = enc[b,t,:] . v[b,:]. Launched with PDL: blocks are
// dispatched while proj still runs; griddep_wait gates the g_vpart reads.
// Inner loop: MLP_p1=4, shfl-in-loop (proven optimal). __ldcs enc stream.
// Block tail computes the (m,sumexp) tile partial.
// ---------------------------------------------------------------------------
__global__ void __launch_bounds__(256)
scores_kernel(const float* __restrict__ enc) {
    const int b    = blockIdx.y;
    const int tile = blockIdx.x;          // 64 t-values per block
    const int tid  = threadIdx.x;         // 256
    const int warp = tid >> 5;
    const int lane = tid & 31;

    griddep_wait();                       // proj results visible after this

    __shared__ float sv[H];
    {
        const float2 p0 = reinterpret_cast<const float2*>(g_vpart[0][b])[tid];
        const float2 p1 = reinterpret_cast<const float2*>(g_vpart[1][b])[tid];
        const float2 p2 = reinterpret_cast<const float2*>(g_vpart[2][b])[tid];
        const float2 p3 = reinterpret_cast<const float2*>(g_vpart[3][b])[tid];
        float2 s;
        s.x = (p0.x + p1.x) + (p2.x + p3.x);
        s.y = (p0.y + p1.y) + (p2.y + p3.y);
        reinterpret_cast<float2*>(sv)[tid] = s;
    }
    __syncthreads();

    const float4* __restrict__ vb = reinterpret_cast<const float4*>(sv);
    const float4* __restrict__ base =
        reinterpret_cast<const float4*>(enc + (size_t)b * T * H);

    __shared__ float s_acc[64];           // this block's 64 raw scores

#pragma unroll
    for (int i = 0; i < 8; ++i) {
        const int t = tile * 64 + warp * 8 + i;
        const float4* __restrict__ row = base + (size_t)t * (H / 4);

        float acc = 0.0f;
#pragma unroll
        for (int k = 0; k < 4; ++k) {
            const float4 x = __ldcs(row + lane + k * 32);
            const float4 w = vb[lane + k * 32];
            acc += x.x * w.x + x.y * w.y + x.z * w.z + x.w * w.w;
        }
#pragma unroll
        for (int off = 16; off; off >>= 1)
            acc += __shfl_xor_sync(0xffffffffu, acc, off);
        if (lane == 0) {
            g_scores[b * T + t] = acc;
            s_acc[warp * 8 + i] = acc;
        }
    }

    // block tail: (m, sumexp) over the 64 scores (off the load path)
    __syncthreads();
    if (tid < 32) {
        const float v0 = s_acc[tid];
        const float v1 = s_acc[tid + 32];
        float m = fmaxf(v0, v1);
#pragma unroll
        for (int off = 16; off; off >>= 1)
            m = fmaxf(m, __shfl_xor_sync(0xffffffffu, m, off));
        float e = __expf(v0 - m) + __expf(v1 - m);
#pragma unroll
        for (int off = 16; off; off >>= 1)
            e += __shfl_xor_sync(0xffffffffu, e, off);
        if (tid == 0) {
            float2 r; r.x = m; r.y = e;
            g_bpart[b][tile] = r;
        }
    }
}

// ---------------------------------------------------------------------------
// Kernel 3: scale pass (PDL-launched). Grid (T/1024, B) = 256 blocks x 256
// threads. Combine 64 tile partials (L2 hits), then exp(x-m)/S.
// ---------------------------------------------------------------------------
__global__ void __launch_bounds__(256)
scale_kernel(float* __restrict__ out) {
    const int b   = blockIdx.y;
    const int seg = blockIdx.x;           // 1024 t-values per block
    const int tid = threadIdx.x;          // 256

    griddep_wait();                       // scores results visible after this

    __shared__ float2 ms;
    if (tid < 32) {
        float2 v = sm_combine(g_bpart[b][tid], g_bpart[b][tid + 32]);
#pragma unroll
        for (int off = 16; off; off >>= 1) {
            float2 o;
            o.x = __shfl_xor_sync(0xffffffffu, v.x, off);
            o.y = __shfl_xor_sync(0xffffffffu, v.y, off);
            v = sm_combine(v, o);
        }
        if (tid == 0) ms = v;
    }
    __syncthreads();

    const float m   = ms.x;
    const float inv = 1.0f / ms.y;

    const int idx = b * T + seg * 1024 + tid * 4;
    const float4 x = *reinterpret_cast<const float4*>(g_scores + idx);
    float4 y;
    y.x = __expf(x.x - m) * inv;
    y.y = __expf(x.y - m) * inv;
    y.z = __expf(x.z - m) * inv;
    y.w = __expf(x.w - m) * inv;
    *reinterpret_cast<float4*>(out + idx) = y;
}

// ---------------------------------------------------------------------------
extern "C" void kernel_launch(void* const* d_in, const int* in_sizes, int n_in,
                              void* d_out, int out_size) {
    const float* hidden = (const float*)d_in[0];   // [B, H]
    const float* enc    = (const float*)d_in[1];   // [B, T, H]
    const float* W      = (const float*)d_in[2];   // [H, H]
    // d_in[3] = bias: cancels under softmax, unused.
    float* out = (float*)d_out;                    // [B, 1, T]

    // Kernel 1: plain launch
    {
        dim3 grid(H / 32, B / 4, OCHUNKS);
        proj_hidden_kernel<<<grid, 256>>>(hidden, W);
    }

    // PDL attribute shared by the two dependent launches
    cudaLaunchAttribute attrs[1];
    attrs[0].id = cudaLaunchAttributeProgrammaticStreamSerialization;
    attrs[0].val.programmaticStreamSerializationAllowed = 1;

    // Kernel 2: scores, PDL on proj
    {
        cudaLaunchConfig_t cfg = {};
        cfg.gridDim  = dim3(T / NTILE, B);
        cfg.blockDim = dim3(256);
        cfg.dynamicSmemBytes = 0;
        cfg.stream = 0;                    // same (default) stream as <<<>>>
        cfg.attrs = attrs;
        cfg.numAttrs = 1;
        cudaLaunchKernelEx(&cfg, scores_kernel, enc);
    }

    // Kernel 3: scale, PDL on scores
    {
        cudaLaunchConfig_t cfg = {};
        cfg.gridDim  = dim3(T / 1024, B);
        cfg.blockDim = dim3(256);
        cfg.dynamicSmemBytes = 0;
        cfg.stream = 0;
        cfg.attrs = attrs;
        cfg.numAttrs = 1;
        cudaLaunchKernelEx(&cfg, scale_kernel, out);
    }
}